// round 5
// baseline (speedup 1.0000x reference)
#include <cuda_runtime.h>
#include <cuda_bf16.h>
#include <cstdint>

#define B_SZ 16
#define D_DIM 128
#define T_SZ 4096
#define KCODES 1024
#define NVEC (B_SZ * T_SZ)
#define ROWS 128
#define NCTA (NVEC / ROWS)
#define NTHR 256
#define CAPT 32
#define MARGIN 0.5f

#define OFF_Q 1
#define OFF_PERP (1 + B_SZ * D_DIM * T_SZ)
#define OFF_IDX (2 + B_SZ * D_DIM * T_SZ)

__device__ float g_cnorm[KCODES];
__device__ __nv_bfloat16 g_cb16[KCODES * D_DIM];
__device__ float g_counts[KCODES];
__device__ float g_loss;

// dynamic smem byte offsets (base 1024-aligned)
#define SO_A 0u         // 128 x 128 bf16, 256B rows, swizzled (32768)
#define SO_B 32768u     // 2 x 128 codes x 256B (65536)
#define SO_XF 98304u    // 128 x 129 fp32 (66048)
#define SO_CN 164352u   // 1024 fp32
#define SO_CAND 168448u // 256 x 32 u16 (16384)
#define SO_BI 184832u   // 128 int
#define SO_RED 185344u  // reduction scratch
#define SMEM_DYN 186432u

__device__ __forceinline__ uint32_t smem_u32(const void* p) {
    uint32_t a;
    asm("{ .reg .u64 t; cvta.to.shared.u64 t, %1; cvt.u32.u64 %0, t; }" : "=r"(a) : "l"(p));
    return a;
}
// 256B-row tile, 16B-chunk XOR swizzle (conflict-free ldmatrix)
__device__ __forceinline__ uint32_t swz(int row, int c16) {
    return ((uint32_t)row << 8) + (uint32_t)((c16 ^ (row & 7)) << 4);
}

#define LDM4(r0, r1, r2, r3, ad) \
    asm volatile("ldmatrix.sync.aligned.m8n8.x4.shared.b16 {%0,%1,%2,%3}, [%4];" \
        : "=r"(r0), "=r"(r1), "=r"(r2), "=r"(r3) : "r"(ad))

#define MMA(c0, c1, c2, c3, a0, a1, a2, a3, b0, b1) \
    asm volatile("mma.sync.aligned.m16n8k16.row.col.f32.bf16.bf16.f32 " \
        "{%0,%1,%2,%3}, {%4,%5,%6,%7}, {%8,%9}, {%0,%1,%2,%3};" \
        : "+f"(c0), "+f"(c1), "+f"(c2), "+f"(c3) \
        : "r"(a0), "r"(a1), "r"(a2), "r"(a3), "r"(b0), "r"(b1))

__device__ __forceinline__ void load_chunk(uint32_t sbB, int chunk, int buf) {
    const char* src0 = (const char*)g_cb16 + (size_t)chunk * 128 * 256;
    uint32_t dst0 = sbB + ((uint32_t)buf << 15);
    for (int u = threadIdx.x; u < 2048; u += NTHR) {
        int code = u >> 4, c16 = u & 15;
        uint32_t dst = dst0 + swz(code, c16);
        const char* src = src0 + code * 256 + c16 * 16;
        asm volatile("cp.async.cg.shared.global [%0], [%1], 16;"
                     :: "r"(dst), "l"(__cvta_generic_to_global(src)) : "memory");
    }
    asm volatile("cp.async.commit_group;" ::: "memory");
}

__global__ void vq_prep(const float* __restrict__ cb) {
    int k = blockIdx.x, t = threadIdx.x;
    float v = cb[k * D_DIM + t];
    g_cb16[k * D_DIM + t] = __float2bfloat16(v);
    float s = v * v;
#pragma unroll
    for (int o = 16; o; o >>= 1) s += __shfl_xor_sync(0xFFFFFFFFu, s, o);
    __shared__ float ws[4];
    if ((t & 31) == 0) ws[t >> 5] = s;
    __syncthreads();
    if (t == 0) {
        g_cnorm[k] = 0.5f * (ws[0] + ws[1] + ws[2] + ws[3]);
        g_counts[k] = 0.0f;
        if (k == 0) g_loss = 0.0f;
    }
}

__global__ __launch_bounds__(NTHR, 1)
void vq_main(const float* __restrict__ in, const float* __restrict__ cb,
             float* __restrict__ out) {
    extern __shared__ char smraw[];
    const int tid = threadIdx.x;
    uint32_t sb_raw = smem_u32(smraw);
    uint32_t sb = (sb_raw + 1023u) & ~1023u;
    char* sm = smraw + (sb - sb_raw);

    float* xf = (float*)(sm + SO_XF);
    float* cn = (float*)(sm + SO_CN);
    unsigned short* cand = (unsigned short*)(sm + SO_CAND);
    int* bi_s = (int*)(sm + SO_BI);
    float* red = (float*)(sm + SO_RED);

    const int bIdx = blockIdx.x >> 5;
    const int t0 = (blockIdx.x & 31) << 7;
    const float* inb = in + (size_t)bIdx * (D_DIM * T_SZ) + t0;

    const int w = tid >> 5, lane = tid & 31;
    const int qr = lane >> 2, qc = lane & 3;
    const int grp = lane >> 3, rr = lane & 7;

    for (int i = tid; i < KCODES; i += NTHR) cn[i] = g_cnorm[i];

    // x tile: fp32 padded + bf16 swizzled (A operand)
    for (int i = tid; i < ROWS * D_DIM; i += NTHR) {
        int d = i >> 7, j = i & 127;
        float v = inb[(size_t)d * T_SZ + j];
        xf[j * 129 + d] = v;
        *(__nv_bfloat16*)(sm + SO_A + swz(j, d >> 3) + ((d & 7) << 1)) = __float2bfloat16(v);
    }
    load_chunk(sb + SO_B, 0, 0);
    __syncthreads();

    // A fragments for this warp's 16 rows (held for whole kernel)
    uint32_t a[32];
    {
        int rw = w << 4;
#pragma unroll
        for (int ks = 0; ks < 8; ++ks) {
            int row = rw + rr + ((grp & 1) << 3);
            uint32_t ad = sb + SO_A + swz(row, 2 * ks + (grp >> 1));
            LDM4(a[4 * ks], a[4 * ks + 1], a[4 * ks + 2], a[4 * ks + 3], ad);
        }
    }

    unsigned short* candp = cand + tid * CAPT;
    float bestLo = -3.0e38f, bestHi = -3.0e38f;
    unsigned int cnt = 0;

    for (int c = 0; c < 8; ++c) {
        if (c < 7) {
            load_chunk(sb + SO_B, c + 1, (c + 1) & 1);
            asm volatile("cp.async.wait_group 1;" ::: "memory");
        } else {
            asm volatile("cp.async.wait_group 0;" ::: "memory");
        }
        __syncthreads();
        uint32_t bbase = sb + SO_B + ((uint32_t)(c & 1) << 15);
        int cbase = c << 7;
#pragma unroll 2
        for (int nb = 0; nb < 16; ++nb) {
            uint32_t bf[16];
            int brow = nb * 8 + rr;
#pragma unroll
            for (int p = 0; p < 4; ++p) {
                uint32_t ad = bbase + swz(brow, 4 * p + grp);
                LDM4(bf[4 * p], bf[4 * p + 1], bf[4 * p + 2], bf[4 * p + 3], ad);
            }
            float c0 = 0.f, c1 = 0.f, c2 = 0.f, c3 = 0.f;
#pragma unroll
            for (int ks = 0; ks < 8; ++ks)
                MMA(c0, c1, c2, c3, a[4 * ks], a[4 * ks + 1], a[4 * ks + 2], a[4 * ks + 3],
                    bf[2 * ks], bf[2 * ks + 1]);
            int g0 = cbase + nb * 8 + 2 * qc;
            float cnA = cn[g0], cnB = cn[g0 + 1];
            float s0 = c0 - cnA, s1 = c1 - cnB, s2 = c2 - cnA, s3 = c3 - cnB;
            // ring buffer: on overflow keep latest (late arrivals are the records)
            if (s0 > bestLo - MARGIN) {
                candp[cnt & (CAPT - 1)] = (unsigned short)g0;
                ++cnt; if (s0 > bestLo) bestLo = s0;
            }
            if (s1 > bestLo - MARGIN) {
                candp[cnt & (CAPT - 1)] = (unsigned short)(g0 + 1);
                ++cnt; if (s1 > bestLo) bestLo = s1;
            }
            if (s2 > bestHi - MARGIN) {
                candp[cnt & (CAPT - 1)] = (unsigned short)(g0 | 0x8000);
                ++cnt; if (s2 > bestHi) bestHi = s2;
            }
            if (s3 > bestHi - MARGIN) {
                candp[cnt & (CAPT - 1)] = (unsigned short)((g0 + 1) | 0x8000);
                ++cnt; if (s3 > bestHi) bestHi = s3;
            }
        }
        __syncthreads();
    }

    // exact fp32 rescore of candidates
    const int rLo = (w << 4) + qr, rHi = rLo + 8;
    float sLo = -3.4e38f, sHi = -3.4e38f;
    int cLo = KCODES, cHi = KCODES;
    {
        unsigned int n = cnt < CAPT ? cnt : CAPT;
        for (unsigned int j = 0; j < n; ++j) {
            unsigned short e = candp[j];
            int code = e & 1023, hi = e >> 15;
            const float* xr = xf + (hi ? rHi : rLo) * 129;
            const float4* q = (const float4*)(cb + (code << 7));
            float a0 = 0.f, a1 = 0.f, a2 = 0.f, a3 = 0.f;
#pragma unroll
            for (int d = 0; d < 32; ++d) {
                float4 v = __ldg(q + d);
                a0 = fmaf(v.x, xr[4 * d + 0], a0);
                a1 = fmaf(v.y, xr[4 * d + 1], a1);
                a2 = fmaf(v.z, xr[4 * d + 2], a2);
                a3 = fmaf(v.w, xr[4 * d + 3], a3);
            }
            float s = (a0 + a1) + (a2 + a3) - cn[code];
            if (hi) { if (s > sHi || (s == sHi && code < cHi)) { sHi = s; cHi = code; } }
            else    { if (s > sLo || (s == sLo && code < cLo)) { sLo = s; cLo = code; } }
        }
    }
    // merge across the 4 lanes sharing each row
#pragma unroll
    for (int o = 1; o <= 2; o <<= 1) {
        float so = __shfl_xor_sync(0xFFFFFFFFu, sLo, o);
        int co = __shfl_xor_sync(0xFFFFFFFFu, cLo, o);
        if (so > sLo || (so == sLo && co < cLo)) { sLo = so; cLo = co; }
        so = __shfl_xor_sync(0xFFFFFFFFu, sHi, o);
        co = __shfl_xor_sync(0xFFFFFFFFu, cHi, o);
        if (so > sHi || (so == sHi && co < cHi)) { sHi = so; cHi = co; }
    }
    if (qc == 0) {
        bi_s[rLo] = cLo;
        bi_s[rHi] = cHi;
        out[OFF_IDX + (size_t)bIdx * T_SZ + t0 + rLo] = (float)cLo;
        out[OFF_IDX + (size_t)bIdx * T_SZ + t0 + rHi] = (float)cHi;
        atomicAdd(&g_counts[cLo], 1.0f);
        atomicAdd(&g_counts[cHi], 1.0f);
    }
    __syncthreads();

    // gather selected codes into xf (overwrite x), accumulate loss
    float lpart = 0.f;
    for (int i = tid; i < ROWS * 32; i += NTHR) {
        int rw = i >> 5, c4 = i & 31;
        int code = bi_s[rw];
        float4 q = __ldg((const float4*)(cb + (code << 7)) + c4);
        float* xp = &xf[rw * 129 + (c4 << 2)];
        float d0 = q.x - xp[0], d1 = q.y - xp[1], d2 = q.z - xp[2], d3 = q.w - xp[3];
        lpart += d0 * d0 + d1 * d1 + d2 * d2 + d3 * d3;
        xp[0] = q.x; xp[1] = q.y; xp[2] = q.z; xp[3] = q.w;
    }
#pragma unroll
    for (int o = 16; o; o >>= 1) lpart += __shfl_xor_sync(0xFFFFFFFFu, lpart, o);
    if (lane == 0) red[w] = lpart;
    __syncthreads();
    if (tid == 0) {
        float s = 0.f;
        for (int q = 0; q < 8; ++q) s += red[q];
        atomicAdd(&g_loss, s);
    }

    // transposed coalesced quantized write
    for (int i = tid; i < ROWS * D_DIM; i += NTHR) {
        int d = i >> 7, j = i & 127;
        out[OFF_Q + (size_t)bIdx * (D_DIM * T_SZ) + (size_t)d * T_SZ + t0 + j] =
            xf[j * 129 + d];
    }
}

__global__ void vq_fin(float* __restrict__ out) {
    __shared__ float sh[256];
    int t = threadIdx.x;
    float h = 0.f;
    for (int k = t; k < KCODES; k += 256) {
        float p = g_counts[k] * (1.0f / (float)NVEC);
        h += p * logf(p + 1e-10f);
    }
    sh[t] = h;
    __syncthreads();
    for (int o = 128; o; o >>= 1) {
        if (t < o) sh[t] += sh[t + o];
        __syncthreads();
    }
    if (t == 0) {
        out[0] = 0.25f * g_loss / (float)(B_SZ * D_DIM * T_SZ);
        out[OFF_PERP] = expf(-sh[0]);
    }
}

extern "C" void kernel_launch(void* const* d_in, const int* in_sizes, int n_in,
                              void* d_out, int out_size) {
    const float* in = (const float*)d_in[0];
    const float* cb = (const float*)d_in[1];
    if (n_in >= 2 && in_sizes[0] == KCODES * D_DIM) {
        const float* t = in; in = cb; cb = t;
    }
    float* out = (float*)d_out;
    cudaFuncSetAttribute(vq_main, cudaFuncAttributeMaxDynamicSharedMemorySize, SMEM_DYN);
    vq_prep<<<KCODES, 128>>>(cb);
    vq_main<<<NCTA, NTHR, SMEM_DYN>>>(in, cb, out);
    vq_fin<<<1, 256>>>(out);
}